// round 17
// baseline (speedup 1.0000x reference)
#include <cuda_runtime.h>
#include <cstdint>

// ============================================================================
// TF32 mma.sync GEMM: out[32768,512] = X @ W^T + bias.
// R16 pipeline (mbarrier producer/consumer, no per-chunk __syncthreads,
// cp.async.mbarrier.arrive.noinc) + NEW: 64x64 warp tiles, 128-thread CTAs
// (2x2 warps), 2 CTAs/SM. Cuts B fragment redundancy 4x->2x => smem crossbar
// traffic -25%, which was co-limiting with the tensor pipe at ~63%.
// acc = 128 regs/thread; launch_bounds(128,2) -> 256 regs, no spills.
// Base: Wperm (pre-rounded+permuted W), zero-cvt vector B frags, scalar+cvt A,
// 3 stages, XOR-swizzled exact-128B B rows.
// BM=BN=128, BK=32, 4 warps, warp tile 64x64, m16n8k8.
// ============================================================================

#define MTOT 32768
#define KTOT 512
#define NTOT 512
#define BM   128
#define BN   128
#define BK   32
#define NKC  (KTOT / BK)     // 16
#define STAGES 3
#define THREADS 128
#define SSA  36              // A smem floats/row (32 data + 4 pad), scalar LDS
#define BROW 32              // B smem floats/row (exact 128B, XOR swizzled)

#define A_TILE (BM * SSA)    // 4608 floats / stage
#define B_TILE (BN * BROW)   // 4096 floats / stage

// float offsets in dynamic smem
#define BIAS_OFF  (STAGES * (A_TILE + B_TILE))          // 26112
#define MBAR_OFF  ((BIAS_OFF + BN) * 4)                 // byte offset, 8B-aligned
// mbarriers: full[0..2] at MBAR_OFF + 8*s, empty[0..2] at MBAR_OFF + 24 + 8*s
#define SMEM_BYTES (MBAR_OFF + 48)

__device__ float Wperm[(size_t)NTOT * KTOT];   // 1MB: tf32-rounded, permuted

__device__ __forceinline__ uint32_t smem_u32(const void* p) {
    return (uint32_t)__cvta_generic_to_shared(p);
}

__device__ __forceinline__ uint32_t tf32rn(float x) {
    uint32_t y;
    asm("cvt.rna.tf32.f32 %0, %1;" : "=r"(y) : "f"(x));
    return y;
}

#define CP_ASYNC_CG(dst_u32, src_ptr)                                         \
    asm volatile("cp.async.cg.shared.global [%0], [%1], 16;"                  \
                 :: "r"(dst_u32), "l"(src_ptr))

__device__ __forceinline__ void mbar_init(uint32_t a, uint32_t n) {
    asm volatile("mbarrier.init.shared.b64 [%0], %1;" :: "r"(a), "r"(n) : "memory");
}
__device__ __forceinline__ void mbar_arrive(uint32_t a) {
    asm volatile("mbarrier.arrive.shared.b64 _, [%0];" :: "r"(a) : "memory");
}
__device__ __forceinline__ void cpasync_mbar_arrive_noinc(uint32_t a) {
    asm volatile("cp.async.mbarrier.arrive.noinc.shared.b64 [%0];"
                 :: "r"(a) : "memory");
}
__device__ __forceinline__ void mbar_wait(uint32_t a, uint32_t parity) {
    asm volatile(
        "{\n\t"
        ".reg .pred P;\n"
        "WL_%=:\n\t"
        "mbarrier.try_wait.parity.acquire.cta.shared::cta.b64 P, [%0], %1, 0x989680;\n\t"
        "@P bra WD_%=;\n\t"
        "bra WL_%=;\n"
        "WD_%=:\n\t"
        "}"
        :: "r"(a), "r"(parity) : "memory");
}

__device__ __forceinline__ void mma_tf32(float* d, const uint32_t* a,
                                         const uint32_t* b) {
    asm volatile(
        "mma.sync.aligned.m16n8k8.row.col.f32.tf32.tf32.f32 "
        "{%0,%1,%2,%3}, {%4,%5,%6,%7}, {%8,%9}, {%0,%1,%2,%3};"
        : "+f"(d[0]), "+f"(d[1]), "+f"(d[2]), "+f"(d[3])
        : "r"(a[0]), "r"(a[1]), "r"(a[2]), "r"(a[3]), "r"(b[0]), "r"(b[1]));
}

// W prepass: Wperm[n][p(k)] = tf32_round(W[n][k]),
// p(k) = (k & ~15) | ((k & 3) << 2) | ((k >> 2) & 3)
__global__ void wprep_kernel(const float* __restrict__ W) {
    const int n = blockIdx.x;
    for (int c = threadIdx.x; c < KTOT; c += blockDim.x) {
        const uint32_t bits = tf32rn(W[n * KTOT + c]);
        const int p = (c & ~15) | ((c & 3) << 2) | ((c >> 2) & 3);
        Wperm[n * KTOT + p] = __uint_as_float(bits);
    }
}

__global__ void __launch_bounds__(THREADS, 2)
linear_tf32_kernel(const float* __restrict__ X, const float* __restrict__ bias,
                   float* __restrict__ out) {
    extern __shared__ float smem[];
    float* As = smem;                        // [STAGES][A_TILE]
    float* Bs = smem + STAGES * A_TILE;      // [STAGES][B_TILE]
    float* bias_s = smem + BIAS_OFF;         // [BN]

    const int tid = threadIdx.x;
    const int wid = tid >> 5;
    const int lid = tid & 31;
    const int g = lid >> 2;          // group id (0..7)
    const int t = lid & 3;           // thread-in-group (0..3)
    const int wm = (wid & 1) * 64;   // warp M offset (2x2 warp grid)
    const int wn = (wid >> 1) * 64;  // warp N offset

    const int n0 = blockIdx.x * BN;
    const int m0 = blockIdx.y * BM;

    const float* Ag = X + (size_t)m0 * KTOT;
    const float* Bg = Wperm + (size_t)n0 * KTOT;

    const uint32_t smb = smem_u32(smem);
    const uint32_t full_mb  = smb + MBAR_OFF;        // +8*s
    const uint32_t empty_mb = smb + MBAR_OFF + 24;   // +8*s

    if (tid < BN) bias_s[tid] = bias[n0 + tid];
    if (tid == 0) {
        #pragma unroll
        for (int s = 0; s < STAGES; s++) {
            mbar_init(full_mb + 8 * s, THREADS);
            mbar_init(empty_mb + 8 * s, THREADS);
        }
    }
    __syncthreads();   // mbarriers + bias visible; only CTA-wide sync in kernel

    const uint32_t as_b = smem_u32(As);
    const uint32_t bs_b = smem_u32(Bs);

    // Staging: 128 threads, 8 x 16B of A + 8 x 16B of B per chunk.
    // granule idx = row*8 + c4; thread covers idx = tid + 128*i.
    const int sr0 = tid >> 3;        // base row; rows sr0 + 16*i
    const int sc4 = tid & 7;

    // -------- prologue: stage chunks 0 and 1 --------
    #pragma unroll
    for (int pc = 0; pc < 2; pc++) {
        const int kb = pc * BK;
        const uint32_t an = as_b + pc * A_TILE * 4;
        const uint32_t bn = bs_b + pc * B_TILE * 4;
        #pragma unroll
        for (int i = 0; i < 8; i++) {
            const int row = sr0 + i * 16;
            CP_ASYNC_CG(an + (row * SSA + sc4 * 4) * 4,
                        Ag + (size_t)row * KTOT + kb + sc4 * 4);
        }
        #pragma unroll
        for (int i = 0; i < 8; i++) {
            const int row = sr0 + i * 16;
            const int c4s = sc4 ^ ((row & 1) << 2);
            CP_ASYNC_CG(bn + (row * BROW + c4s * 4) * 4,
                        Bg + (size_t)row * KTOT + kb + sc4 * 4);
        }
        cpasync_mbar_arrive_noinc(full_mb + 8 * pc);
    }

    float acc[4][8][4];
    #pragma unroll
    for (int mi = 0; mi < 4; mi++)
        #pragma unroll
        for (int nj = 0; nj < 8; nj++)
            #pragma unroll
            for (int e = 0; e < 4; e++) acc[mi][nj][e] = 0.0f;

    int s = 0;                 // kc % 3
    uint32_t fullmask = 0;     // phase bits per stage (full waits)
    uint32_t emptymask = 0;    // phase bits per stage (empty waits)

    for (int kc = 0; kc < NKC; kc++) {
        // ---- consume: wait chunk kc staged ----
        mbar_wait(full_mb + 8 * s, (fullmask >> s) & 1);
        fullmask ^= 1u << s;

        const float* At = As + s * A_TILE;
        const float* Bt = Bs + s * B_TILE;

        #pragma unroll
        for (int G = 0; G < 2; G++) {   // two 16-K groups per chunk
            // B fragments: 8 x LDS.128 (swizzled granule), zero cvt.
            uint32_t bf0[8][2], bf1[8][2];
            #pragma unroll
            for (int nj = 0; nj < 8; nj++) {
                const int n = wn + nj * 8 + g;
                const int c4 = (4 * G + t) ^ ((n & 1) << 2);
                const float4 v = *reinterpret_cast<const float4*>(
                    Bt + n * BROW + c4 * 4);
                bf0[nj][0] = __float_as_uint(v.x);
                bf0[nj][1] = __float_as_uint(v.y);
                bf1[nj][0] = __float_as_uint(v.z);
                bf1[nj][1] = __float_as_uint(v.w);
            }
            #pragma unroll
            for (int ks = 0; ks < 2; ks++) {   // K=8 slices within group
                const int k = G * 16 + ks * 8;
                #pragma unroll
                for (int mi = 0; mi < 4; mi++) {
                    const int r = wm + mi * 16 + g;
                    uint32_t af[4];
                    af[0] = tf32rn(At[r * SSA + k + t]);
                    af[1] = tf32rn(At[(r + 8) * SSA + k + t]);
                    af[2] = tf32rn(At[r * SSA + k + t + 4]);
                    af[3] = tf32rn(At[(r + 8) * SSA + k + t + 4]);
                    #pragma unroll
                    for (int nj = 0; nj < 8; nj++)
                        mma_tf32(acc[mi][nj], af,
                                 ks ? bf1[nj] : bf0[nj]);
                }
            }
        }

        // ---- release stage s (arrive has release semantics) ----
        mbar_arrive(empty_mb + 8 * s);

        // ---- produce: stage chunk kc+2 ----
        const int c = kc + 2;
        if (c < NKC) {
            int sn = s + 2; if (sn >= STAGES) sn -= STAGES;
            if (c >= STAGES) {   // stage reuse: wait until all consumed c-3
                mbar_wait(empty_mb + 8 * sn, (emptymask >> sn) & 1);
                emptymask ^= 1u << sn;
            }
            const int kb = c * BK;
            const uint32_t an = as_b + sn * A_TILE * 4;
            const uint32_t bn = bs_b + sn * B_TILE * 4;
            #pragma unroll
            for (int i = 0; i < 8; i++) {
                const int row = sr0 + i * 16;
                CP_ASYNC_CG(an + (row * SSA + sc4 * 4) * 4,
                            Ag + (size_t)row * KTOT + kb + sc4 * 4);
            }
            #pragma unroll
            for (int i = 0; i < 8; i++) {
                const int row = sr0 + i * 16;
                const int c4s = sc4 ^ ((row & 1) << 2);
                CP_ASYNC_CG(bn + (row * BROW + c4s * 4) * 4,
                            Bg + (size_t)row * KTOT + kb + sc4 * 4);
            }
            cpasync_mbar_arrive_noinc(full_mb + 8 * sn);
        }

        if (++s == STAGES) s = 0;
    }

    // -------- epilogue: add bias, store float2 (per-warp, no sync needed) ----
    #pragma unroll
    for (int mi = 0; mi < 4; mi++) {
        const int r0 = m0 + wm + mi * 16 + g;
        #pragma unroll
        for (int nj = 0; nj < 8; nj++) {
            const int cl = wn + nj * 8 + 2 * t;
            const float bx = bias_s[cl];
            const float by = bias_s[cl + 1];
            float2 v0 = make_float2(acc[mi][nj][0] + bx, acc[mi][nj][1] + by);
            float2 v1 = make_float2(acc[mi][nj][2] + bx, acc[mi][nj][3] + by);
            *reinterpret_cast<float2*>(out + (size_t)r0 * NTOT + n0 + cl) = v0;
            *reinterpret_cast<float2*>(out + (size_t)(r0 + 8) * NTOT + n0 + cl) = v1;
        }
    }
}

extern "C" void kernel_launch(void* const* d_in, const int* in_sizes, int n_in,
                              void* d_out, int out_size) {
    const float* X    = (const float*)d_in[0];
    const float* Wt   = (const float*)d_in[1];
    const float* bias = (const float*)d_in[2];
    float* out = (float*)d_out;

    const int Mrows = in_sizes[0] / KTOT;   // 32768

    wprep_kernel<<<NTOT, 256>>>(Wt);

    cudaFuncSetAttribute(linear_tf32_kernel,
                         cudaFuncAttributeMaxDynamicSharedMemorySize, SMEM_BYTES);

    dim3 grid(NTOT / BN, Mrows / BM);  // (4, 256)
    linear_tf32_kernel<<<grid, THREADS, SMEM_BYTES>>>(X, bias, out);
}